// round 1
// baseline (speedup 1.0000x reference)
#include <cuda_runtime.h>
#include <math.h>

// Problem constants
#define HIDK   2048
#define NH     16
#define NKV    4
#define HD     128
#define GQ     (NH / NKV)        // 4
#define BATCH  2
#define SEQ    2048
#define MROWS  (BATCH * SEQ)     // 4096

// Scratch (device globals; no allocation allowed)
__device__ float g_q[(size_t)MROWS * NH * HD];     // 4096 x 2048
__device__ float g_k[(size_t)MROWS * NKV * HD];    // 4096 x 512
__device__ float g_v[(size_t)MROWS * NKV * HD];    // 4096 x 512
__device__ float g_attn[(size_t)MROWS * NH * HD];  // 4096 x 2048

// ---------------------------------------------------------------------------
// SGEMM: C[M,N] = A[M,K] @ B[K,N] + bias[N]
// 128x128 block tile, BK=16, 256 threads, 8x8 per-thread micro-tile.
// M,N multiples of 128; K multiple of 16 (true for all our shapes).
// ---------------------------------------------------------------------------
__global__ __launch_bounds__(256)
void sgemm_bias_kernel(const float* __restrict__ A,
                       const float* __restrict__ B,
                       const float* __restrict__ bias,
                       float* __restrict__ C,
                       int M, int N, int K)
{
    const int BM = 128, BN = 128, BK = 16;
    __shared__ float As[BK][BM];   // A tile stored k-major (transposed)
    __shared__ float Bs[BK][BN];

    const int tid = threadIdx.x;
    const int tx = tid & 15;       // 0..15 -> col groups of 8
    const int ty = tid >> 4;       // 0..15 -> row groups of 8
    const int rowBase = blockIdx.y * BM;
    const int colBase = blockIdx.x * BN;

    float acc[8][8];
#pragma unroll
    for (int i = 0; i < 8; ++i)
#pragma unroll
        for (int j = 0; j < 8; ++j) acc[i][j] = 0.f;

    const float* Aptr = A + (size_t)rowBase * K;
    const float* Bptr = B + colBase;

    for (int k0 = 0; k0 < K; k0 += BK) {
        // Load A tile 128x16 (2 float4 per thread), store transposed.
#pragma unroll
        for (int it = 0; it < 2; ++it) {
            int idx = tid + it * 256;          // 0..511
            int ar = idx >> 2;                 // 0..127
            int ac = (idx & 3) << 2;           // 0,4,8,12
            float4 av = *(const float4*)(Aptr + (size_t)ar * K + k0 + ac);
            As[ac + 0][ar] = av.x;
            As[ac + 1][ar] = av.y;
            As[ac + 2][ar] = av.z;
            As[ac + 3][ar] = av.w;
            int br = idx >> 5;                 // 0..15
            int bc = (idx & 31) << 2;          // 0..124
            *(float4*)(&Bs[br][bc]) =
                *(const float4*)(Bptr + (size_t)(k0 + br) * N + bc);
        }
        __syncthreads();

#pragma unroll
        for (int kk = 0; kk < BK; ++kk) {
            float4 a0 = *(const float4*)&As[kk][ty * 8];
            float4 a1 = *(const float4*)&As[kk][ty * 8 + 4];
            float4 b0 = *(const float4*)&Bs[kk][tx * 8];
            float4 b1 = *(const float4*)&Bs[kk][tx * 8 + 4];
            float ra[8] = {a0.x, a0.y, a0.z, a0.w, a1.x, a1.y, a1.z, a1.w};
            float rb[8] = {b0.x, b0.y, b0.z, b0.w, b1.x, b1.y, b1.z, b1.w};
#pragma unroll
            for (int i = 0; i < 8; ++i)
#pragma unroll
                for (int j = 0; j < 8; ++j)
                    acc[i][j] += ra[i] * rb[j];
        }
        __syncthreads();
    }

    // Epilogue: add bias, vectorized stores.
#pragma unroll
    for (int i = 0; i < 8; ++i) {
        int row = rowBase + ty * 8 + i;
        float* Crow = C + (size_t)row * N + colBase + tx * 8;
        const float* brow = bias + colBase + tx * 8;
        float4 c0, c1;
        c0.x = acc[i][0] + brow[0];
        c0.y = acc[i][1] + brow[1];
        c0.z = acc[i][2] + brow[2];
        c0.w = acc[i][3] + brow[3];
        c1.x = acc[i][4] + brow[4];
        c1.y = acc[i][5] + brow[5];
        c1.z = acc[i][6] + brow[6];
        c1.w = acc[i][7] + brow[7];
        *(float4*)(Crow)     = c0;
        *(float4*)(Crow + 4) = c1;
    }
}

// ---------------------------------------------------------------------------
// Flash attention (fp32, causal, GQA). One block per (q-tile, q-head, batch).
// Br=Bc=64, 256 threads. Q/K stored d-major in SMEM (LDS.128 operand fetch),
// P stored transposed so the PV GEMM also gets vector loads.
// ---------------------------------------------------------------------------
#define BR   64
#define BC   64
#define SPAD 68   // padded row length (multiple of 4 for float4 alignment)

__global__ __launch_bounds__(256)
void flash_attn_kernel(const float* __restrict__ Q,
                       const float* __restrict__ Kg,
                       const float* __restrict__ Vg,
                       float* __restrict__ Og)
{
    extern __shared__ float sm[];
    float* Qs  = sm;                       // [HD][SPAD]  (d-major)
    float* Ks  = Qs + HD * SPAD;           // [HD][SPAD]  (d-major)
    float* Vs  = Ks + HD * SPAD;           // [BC][HD]    (natural)
    float* Ps  = Vs + BC * HD;             // [BC][SPAD]  (col-major: Ps[k][row])
    float* osc = Ps + BC * SPAD;           // [BR] scale / inv-l scratch

    const int tid = threadIdx.x;
    const int tx = tid & 15;   // 0..15 -> key cols (x4) / out cols (x8)
    const int ty = tid >> 4;   // 0..15 -> query rows (x4)
    const int qt = blockIdx.x;
    const int qh = blockIdx.y;
    const int b  = blockIdx.z;
    const int kvh = qh >> 2;   // qh / GQ

    const float scale = 0.08838834764831845f; // 1/sqrt(128)

    // Load Q tile (64 x 128), transpose to d-major, pre-scale.
    const float* Qbase = Q + ((size_t)(b * SEQ + qt * BR) * NH + qh) * HD;
#pragma unroll
    for (int it = 0; it < 8; ++it) {
        int idx = tid + it * 256;       // 0..2047 (float4 units)
        int r = idx >> 5;               // 0..63
        int c = (idx & 31) << 2;        // 0..124
        float4 v = *(const float4*)(Qbase + (size_t)r * NH * HD + c);
        Qs[(c + 0) * SPAD + r] = v.x * scale;
        Qs[(c + 1) * SPAD + r] = v.y * scale;
        Qs[(c + 2) * SPAD + r] = v.z * scale;
        Qs[(c + 3) * SPAD + r] = v.w * scale;
    }

    float o[4][8];
#pragma unroll
    for (int i = 0; i < 4; ++i)
#pragma unroll
        for (int j = 0; j < 8; ++j) o[i][j] = 0.f;

    float m_run = -1e30f, l_run = 0.f;   // valid in threads tid < BR

    for (int kt = 0; kt <= qt; ++kt) {
        // Load K (d-major) and V (natural) tiles.
        const float* Kbase = Kg + ((size_t)(b * SEQ + kt * BC) * NKV + kvh) * HD;
        const float* Vbase = Vg + ((size_t)(b * SEQ + kt * BC) * NKV + kvh) * HD;
#pragma unroll
        for (int it = 0; it < 8; ++it) {
            int idx = tid + it * 256;
            int r = idx >> 5;
            int c = (idx & 31) << 2;
            float4 kv = *(const float4*)(Kbase + (size_t)r * NKV * HD + c);
            Ks[(c + 0) * SPAD + r] = kv.x;
            Ks[(c + 1) * SPAD + r] = kv.y;
            Ks[(c + 2) * SPAD + r] = kv.z;
            Ks[(c + 3) * SPAD + r] = kv.w;
            float4 vv = *(const float4*)(Vbase + (size_t)r * NKV * HD + c);
            *(float4*)(Vs + r * HD + c) = vv;
        }
        __syncthreads();

        // S = Q @ K^T  (4x4 micro-tile per thread)
        float s[4][4];
#pragma unroll
        for (int i = 0; i < 4; ++i)
#pragma unroll
            for (int j = 0; j < 4; ++j) s[i][j] = 0.f;

#pragma unroll 8
        for (int d = 0; d < HD; ++d) {
            float4 qv = *(const float4*)(Qs + d * SPAD + ty * 4);
            float4 kv = *(const float4*)(Ks + d * SPAD + tx * 4);
            s[0][0] += qv.x * kv.x; s[0][1] += qv.x * kv.y; s[0][2] += qv.x * kv.z; s[0][3] += qv.x * kv.w;
            s[1][0] += qv.y * kv.x; s[1][1] += qv.y * kv.y; s[1][2] += qv.y * kv.z; s[1][3] += qv.y * kv.w;
            s[2][0] += qv.z * kv.x; s[2][1] += qv.z * kv.y; s[2][2] += qv.z * kv.z; s[2][3] += qv.z * kv.w;
            s[3][0] += qv.w * kv.x; s[3][1] += qv.w * kv.y; s[3][2] += qv.w * kv.z; s[3][3] += qv.w * kv.w;
        }

        // Causal mask (diagonal tile only).
        if (kt == qt) {
#pragma unroll
            for (int i = 0; i < 4; ++i)
#pragma unroll
                for (int j = 0; j < 4; ++j)
                    if (tx * 4 + j > ty * 4 + i) s[i][j] = -1e30f;
        }

        // Write scores transposed: Ps[col][row].
#pragma unroll
        for (int j = 0; j < 4; ++j)
#pragma unroll
            for (int i = 0; i < 4; ++i)
                Ps[(tx * 4 + j) * SPAD + (ty * 4 + i)] = s[i][j];
        __syncthreads();

        // Online softmax: one thread per query row.
        if (tid < BR) {
            float rmax = -1e30f;
#pragma unroll 8
            for (int j = 0; j < BC; ++j)
                rmax = fmaxf(rmax, Ps[j * SPAD + tid]);
            float mn = fmaxf(m_run, rmax);
            float corr = __expf(m_run - mn);
            float sum = 0.f;
#pragma unroll 8
            for (int j = 0; j < BC; ++j) {
                float p = __expf(Ps[j * SPAD + tid] - mn);
                Ps[j * SPAD + tid] = p;
                sum += p;
            }
            l_run = l_run * corr + sum;
            m_run = mn;
            osc[tid] = corr;
        }
        __syncthreads();

        // Rescale accumulator, then O += P @ V.
        float c0 = osc[ty * 4 + 0];
        float c1 = osc[ty * 4 + 1];
        float c2 = osc[ty * 4 + 2];
        float c3 = osc[ty * 4 + 3];
#pragma unroll
        for (int j = 0; j < 8; ++j) {
            o[0][j] *= c0; o[1][j] *= c1; o[2][j] *= c2; o[3][j] *= c3;
        }

#pragma unroll 8
        for (int kk = 0; kk < BC; ++kk) {
            float4 p  = *(const float4*)(Ps + kk * SPAD + ty * 4);
            float4 v0 = *(const float4*)(Vs + kk * HD + tx * 8);
            float4 v1 = *(const float4*)(Vs + kk * HD + tx * 8 + 4);
            o[0][0] += p.x * v0.x; o[0][1] += p.x * v0.y; o[0][2] += p.x * v0.z; o[0][3] += p.x * v0.w;
            o[0][4] += p.x * v1.x; o[0][5] += p.x * v1.y; o[0][6] += p.x * v1.z; o[0][7] += p.x * v1.w;
            o[1][0] += p.y * v0.x; o[1][1] += p.y * v0.y; o[1][2] += p.y * v0.z; o[1][3] += p.y * v0.w;
            o[1][4] += p.y * v1.x; o[1][5] += p.y * v1.y; o[1][6] += p.y * v1.z; o[1][7] += p.y * v1.w;
            o[2][0] += p.z * v0.x; o[2][1] += p.z * v0.y; o[2][2] += p.z * v0.z; o[2][3] += p.z * v0.w;
            o[2][4] += p.z * v1.x; o[2][5] += p.z * v1.y; o[2][6] += p.z * v1.z; o[2][7] += p.z * v1.w;
            o[3][0] += p.w * v0.x; o[3][1] += p.w * v0.y; o[3][2] += p.w * v0.z; o[3][3] += p.w * v0.w;
            o[3][4] += p.w * v1.x; o[3][5] += p.w * v1.y; o[3][6] += p.w * v1.z; o[3][7] += p.w * v1.w;
        }
        __syncthreads();
    }

    // Final 1/l normalization.
    if (tid < BR) osc[tid] = 1.f / l_run;
    __syncthreads();
    float i0 = osc[ty * 4 + 0];
    float i1 = osc[ty * 4 + 1];
    float i2 = osc[ty * 4 + 2];
    float i3 = osc[ty * 4 + 3];

    float* Obase = Og + ((size_t)(b * SEQ + qt * BR) * NH + qh) * HD;
#pragma unroll
    for (int i = 0; i < 4; ++i) {
        float inv = (i == 0) ? i0 : (i == 1) ? i1 : (i == 2) ? i2 : i3;
        float* row = Obase + (size_t)(ty * 4 + i) * NH * HD + tx * 8;
        float4 r0, r1;
        r0.x = o[i][0] * inv; r0.y = o[i][1] * inv; r0.z = o[i][2] * inv; r0.w = o[i][3] * inv;
        r1.x = o[i][4] * inv; r1.y = o[i][5] * inv; r1.z = o[i][6] * inv; r1.w = o[i][7] * inv;
        *(float4*)(row)     = r0;
        *(float4*)(row + 4) = r1;
    }
}

// ---------------------------------------------------------------------------
// Launcher
// ---------------------------------------------------------------------------
extern "C" void kernel_launch(void* const* d_in, const int* in_sizes, int n_in,
                              void* d_out, int out_size)
{
    const float* x  = (const float*)d_in[0];
    const float* wq = (const float*)d_in[1];
    const float* bq = (const float*)d_in[2];
    const float* wk = (const float*)d_in[3];
    const float* bk = (const float*)d_in[4];
    const float* wv = (const float*)d_in[5];
    const float* bv = (const float*)d_in[6];
    const float* wo = (const float*)d_in[7];
    const float* bo = (const float*)d_in[8];
    float* out = (float*)d_out;

    float *q, *k, *v, *attn;
    cudaGetSymbolAddress((void**)&q,    g_q);
    cudaGetSymbolAddress((void**)&k,    g_k);
    cudaGetSymbolAddress((void**)&v,    g_v);
    cudaGetSymbolAddress((void**)&attn, g_attn);

    // Projections
    {
        dim3 gq(HIDK / 128, MROWS / 128);      // (16, 32)
        sgemm_bias_kernel<<<gq, 256>>>(x, wq, bq, q, MROWS, NH * HD, HIDK);
        dim3 gk((NKV * HD) / 128, MROWS / 128); // (4, 32)
        sgemm_bias_kernel<<<gk, 256>>>(x, wk, bk, k, MROWS, NKV * HD, HIDK);
        sgemm_bias_kernel<<<gk, 256>>>(x, wv, bv, v, MROWS, NKV * HD, HIDK);
    }

    // Attention
    {
        size_t smem = (size_t)(2 * HD * SPAD + BC * HD + BC * SPAD + BR) * sizeof(float);
        cudaFuncSetAttribute(flash_attn_kernel,
                             cudaFuncAttributeMaxDynamicSharedMemorySize, (int)smem);
        dim3 ga(SEQ / BR, NH, BATCH);           // (32, 16, 2)
        flash_attn_kernel<<<ga, 256, smem>>>(q, k, v, attn);
    }

    // Output projection
    {
        dim3 go(HIDK / 128, MROWS / 128);       // (16, 32)
        sgemm_bias_kernel<<<go, 256>>>(attn, wo, bo, out, MROWS, HIDK, HIDK);
    }
}

// round 2
// speedup vs baseline: 2.3460x; 2.3460x over previous
#include <cuda_runtime.h>
#include <math.h>
#include <stdint.h>

// Problem constants
#define HIDK   2048
#define NH     16
#define NKV    4
#define HD     128
#define BATCH  2
#define SEQ    2048
#define MROWS  (BATCH * SEQ)     // 4096

// Scratch (device globals; no allocation allowed)
__device__ float g_q[(size_t)MROWS * NH * HD];
__device__ float g_k[(size_t)MROWS * NKV * HD];
__device__ float g_v[(size_t)MROWS * NKV * HD];
__device__ float g_attn[(size_t)MROWS * NH * HD];

// ---------------------------------------------------------------------------
// Common PTX helpers
// ---------------------------------------------------------------------------
__device__ __forceinline__ uint32_t f2tf(float x) {
    uint32_t r;
    asm("cvt.rna.tf32.f32 %0, %1;" : "=r"(r) : "f"(x));
    return r;
}

__device__ __forceinline__ void mma_tf32(float c[4],
                                         uint32_t a0, uint32_t a1, uint32_t a2, uint32_t a3,
                                         uint32_t b0, uint32_t b1) {
    asm volatile(
        "mma.sync.aligned.m16n8k8.row.col.f32.tf32.tf32.f32 "
        "{%0,%1,%2,%3}, {%4,%5,%6,%7}, {%8,%9}, {%0,%1,%2,%3};"
        : "+f"(c[0]), "+f"(c[1]), "+f"(c[2]), "+f"(c[3])
        : "r"(a0), "r"(a1), "r"(a2), "r"(a3), "r"(b0), "r"(b1));
}

__device__ __forceinline__ uint32_t smaddr(const void* p) {
    return (uint32_t)__cvta_generic_to_shared(p);
}

#define CPA16(dst, src) asm volatile("cp.async.cg.shared.global [%0], [%1], 16;\n" :: "r"(dst), "l"(src))
#define CPCOMMIT()      asm volatile("cp.async.commit_group;\n")
#define CPWAIT1()       asm volatile("cp.async.wait_group 1;\n" ::: "memory")
#define CPWAIT0()       asm volatile("cp.async.wait_group 0;\n" ::: "memory")

// ---------------------------------------------------------------------------
// TF32 tensor-core GEMM: C[M,N] = A[M,K] @ B[K,N] + bias[N]
// 128x128 block tile, BK=32, 256 threads (8 warps, 4x2), warp tile 32x64.
// Double-buffered cp.async pipeline. M,N mult of 128, K mult of 32.
// ---------------------------------------------------------------------------
#define GLA 36    // A smem row pitch (128 x 32 tile), LA%32==4 -> conflict-free frags
#define GLB 136   // B smem row pitch (32 x 128 tile), LB%32==8 -> conflict-free frags

__global__ __launch_bounds__(256)
void tf32_gemm_bias(const float* __restrict__ A,
                    const float* __restrict__ B,
                    const float* __restrict__ bias,
                    float* __restrict__ C,
                    int M, int N, int K)
{
    extern __shared__ float sm[];
    float* As = sm;                      // [2][128*GLA]
    float* Bs = sm + 2 * 128 * GLA;      // [2][32*GLB]

    const int tid  = threadIdx.x;
    const int lane = tid & 31;
    const int warp = tid >> 5;
    const int wr = warp & 3;             // warp row: 4 -> 32 rows each
    const int wc = warp >> 2;            // warp col: 2 -> 64 cols each
    const int qr = lane >> 2;            // 0..7
    const int qc = lane & 3;             // 0..3
    const int rowBase = blockIdx.y * 128;
    const int colBase = blockIdx.x * 128;

    float acc[2][8][4];
#pragma unroll
    for (int m = 0; m < 2; ++m)
#pragma unroll
        for (int n = 0; n < 8; ++n)
#pragma unroll
            for (int i = 0; i < 4; ++i) acc[m][n][i] = 0.f;

    const int steps = K >> 5;

    // stage issue
    {
        float* as = As;
        float* bs = Bs;
#pragma unroll
        for (int it = 0; it < 4; ++it) {
            int idx = it * 256 + tid;
            int r = idx >> 3, c = (idx & 7) << 2;
            CPA16(smaddr(as + r * GLA + c), A + (size_t)(rowBase + r) * K + c);
            int rb = idx >> 5, cb = (idx & 31) << 2;
            CPA16(smaddr(bs + rb * GLB + cb), B + (size_t)rb * N + colBase + cb);
        }
        CPCOMMIT();
    }

    for (int s = 0; s < steps; ++s) {
        if (s + 1 < steps) {
            int k0 = (s + 1) << 5;
            float* as = As + ((s + 1) & 1) * 128 * GLA;
            float* bs = Bs + ((s + 1) & 1) * 32 * GLB;
#pragma unroll
            for (int it = 0; it < 4; ++it) {
                int idx = it * 256 + tid;
                int r = idx >> 3, c = (idx & 7) << 2;
                CPA16(smaddr(as + r * GLA + c), A + (size_t)(rowBase + r) * K + k0 + c);
                int rb = idx >> 5, cb = (idx & 31) << 2;
                CPA16(smaddr(bs + rb * GLB + cb), B + (size_t)(k0 + rb) * N + colBase + cb);
            }
            CPCOMMIT();
            CPWAIT1();
        } else {
            CPWAIT0();
        }
        __syncthreads();

        const float* as = As + (s & 1) * 128 * GLA + (wr * 32) * GLA;
        const float* bs = Bs + (s & 1) * 32 * GLB + wc * 64;

#pragma unroll
        for (int kk = 0; kk < 4; ++kk) {
            uint32_t af[2][4];
#pragma unroll
            for (int m = 0; m < 2; ++m) {
                const float* ap = as + (m * 16 + qr) * GLA + kk * 8 + qc;
                af[m][0] = f2tf(ap[0]);
                af[m][1] = f2tf(ap[8 * GLA]);
                af[m][2] = f2tf(ap[4]);
                af[m][3] = f2tf(ap[8 * GLA + 4]);
            }
#pragma unroll
            for (int n = 0; n < 8; ++n) {
                const float* bp = bs + (kk * 8 + qc) * GLB + n * 8 + qr;
                uint32_t b0 = f2tf(bp[0]);
                uint32_t b1 = f2tf(bp[4 * GLB]);
                mma_tf32(acc[0][n], af[0][0], af[0][1], af[0][2], af[0][3], b0, b1);
                mma_tf32(acc[1][n], af[1][0], af[1][1], af[1][2], af[1][3], b0, b1);
            }
        }
        __syncthreads();
    }

    // Epilogue
#pragma unroll
    for (int m = 0; m < 2; ++m) {
        int row = rowBase + wr * 32 + m * 16 + qr;
#pragma unroll
        for (int n = 0; n < 8; ++n) {
            int col = colBase + wc * 64 + n * 8 + qc * 2;
            float bx = bias[col], by = bias[col + 1];
            float2 v0 = make_float2(acc[m][n][0] + bx, acc[m][n][1] + by);
            float2 v1 = make_float2(acc[m][n][2] + bx, acc[m][n][3] + by);
            *(float2*)(C + (size_t)row * N + col)       = v0;
            *(float2*)(C + (size_t)(row + 8) * N + col) = v1;
        }
    }
}

// ---------------------------------------------------------------------------
// Flash attention, tf32 tensor cores for QK^T and PV, fp32 online softmax.
// Block: (q-tile 64) x (head) x (batch); 256 threads = 8 warps (4x2).
// ---------------------------------------------------------------------------
#define FBR 64
#define FBC 64
#define FLQ 132   // Qs pitch   (rows x d), %32==4
#define FLK 72    // Ks pitch   (d x tokens), %32==8
#define FLV 136   // Vs pitch   (tokens x d), %32==8
#define FLP 68    // Ps pitch   (rows x tokens), %32==4

__global__ __launch_bounds__(256)
void flash_attn_tf32_kernel(const float* __restrict__ Q,
                            const float* __restrict__ Kg,
                            const float* __restrict__ Vg,
                            float* __restrict__ Og)
{
    extern __shared__ float sm[];
    float* Qs  = sm;                       // [64][FLQ]
    float* Ks  = Qs + FBR * FLQ;           // [128][FLK]  (d-major)
    float* Vs  = Ks + HD * FLK;            // [64][FLV]
    float* Ps  = Vs + FBC * FLV;           // [64][FLP]
    float* ms  = Ps + FBR * FLP;           // [64]
    float* ls  = ms + FBR;                 // [64]
    float* osc = ls + FBR;                 // [64]

    const int tid  = threadIdx.x;
    const int lane = tid & 31;
    const int warp = tid >> 5;
    const int wr = warp & 3;               // 4 warp rows x 16
    const int wc = warp >> 2;              // 2 warp cols
    const int qr = lane >> 2;
    const int qc = lane & 3;

    const int qt  = blockIdx.x;
    const int qh  = blockIdx.y;
    const int b   = blockIdx.z;
    const int kvh = qh >> 2;

    const float scale = 0.08838834764831845f; // 1/sqrt(128)

    // Load Q tile (64 x 128), pre-scaled, row-major.
    const float* Qbase = Q + ((size_t)(b * SEQ + qt * FBR) * NH + qh) * HD;
#pragma unroll
    for (int it = 0; it < 8; ++it) {
        int idx = it * 256 + tid;
        int r = idx >> 5;
        int c = (idx & 31) << 2;
        float4 v = *(const float4*)(Qbase + (size_t)r * NH * HD + c);
        v.x *= scale; v.y *= scale; v.z *= scale; v.w *= scale;
        *(float4*)(Qs + r * FLQ + c) = v;
    }
    if (tid < FBR) { ms[tid] = -1e30f; ls[tid] = 0.f; }

    float o[8][4];
#pragma unroll
    for (int n = 0; n < 8; ++n)
#pragma unroll
        for (int i = 0; i < 4; ++i) o[n][i] = 0.f;

    for (int kt = 0; kt <= qt; ++kt) {
        __syncthreads();   // prior PV / softmax reads done before overwrite

        const float* Kbase = Kg + ((size_t)(b * SEQ + kt * FBC) * NKV + kvh) * HD;
        const float* Vbase = Vg + ((size_t)(b * SEQ + kt * FBC) * NKV + kvh) * HD;
#pragma unroll
        for (int it = 0; it < 8; ++it) {
            int idx = it * 256 + tid;
            int r = idx >> 5;           // token 0..63
            int c = (idx & 31) << 2;    // d
            float4 kv = *(const float4*)(Kbase + (size_t)r * NKV * HD + c);
            Ks[(c + 0) * FLK + r] = kv.x;
            Ks[(c + 1) * FLK + r] = kv.y;
            Ks[(c + 2) * FLK + r] = kv.z;
            Ks[(c + 3) * FLK + r] = kv.w;
            float4 vv = *(const float4*)(Vbase + (size_t)r * NKV * HD + c);
            *(float4*)(Vs + r * FLV + c) = vv;
        }
        __syncthreads();

        // --- S = Q @ K^T (warp: 16 rows x 32 cols) ---
        float sacc[4][4];
#pragma unroll
        for (int n = 0; n < 4; ++n)
#pragma unroll
            for (int i = 0; i < 4; ++i) sacc[n][i] = 0.f;

        const float* qsw = Qs + (wr * 16) * FLQ;
#pragma unroll
        for (int kk = 0; kk < 16; ++kk) {
            const float* ap = qsw + qr * FLQ + kk * 8 + qc;
            uint32_t a0 = f2tf(ap[0]);
            uint32_t a1 = f2tf(ap[8 * FLQ]);
            uint32_t a2 = f2tf(ap[4]);
            uint32_t a3 = f2tf(ap[8 * FLQ + 4]);
#pragma unroll
            for (int n = 0; n < 4; ++n) {
                const float* bp = Ks + (kk * 8 + qc) * FLK + wc * 32 + n * 8 + qr;
                uint32_t b0 = f2tf(bp[0]);
                uint32_t b1 = f2tf(bp[4 * FLK]);
                mma_tf32(sacc[n], a0, a1, a2, a3, b0, b1);
            }
        }

        // Causal mask (diagonal tile only) + store to Ps (row-major).
        int row0 = wr * 16 + qr;
        if (kt == qt) {
#pragma unroll
            for (int n = 0; n < 4; ++n) {
                int col = wc * 32 + n * 8 + qc * 2;
                if (col > row0)         sacc[n][0] = -1e30f;
                if (col + 1 > row0)     sacc[n][1] = -1e30f;
                if (col > row0 + 8)     sacc[n][2] = -1e30f;
                if (col + 1 > row0 + 8) sacc[n][3] = -1e30f;
            }
        }
#pragma unroll
        for (int n = 0; n < 4; ++n) {
            int col = wc * 32 + n * 8 + qc * 2;
            Ps[row0 * FLP + col]           = sacc[n][0];
            Ps[row0 * FLP + col + 1]       = sacc[n][1];
            Ps[(row0 + 8) * FLP + col]     = sacc[n][2];
            Ps[(row0 + 8) * FLP + col + 1] = sacc[n][3];
        }
        __syncthreads();

        // --- online softmax: 4 threads per row, 16 cols each ---
        {
            int row = tid >> 2;
            int cb  = (tid & 3) * 16;
            float* pr = Ps + row * FLP + cb;
            float rmax = -1e30f;
#pragma unroll
            for (int j = 0; j < 16; ++j) rmax = fmaxf(rmax, pr[j]);
            rmax = fmaxf(rmax, __shfl_xor_sync(0xffffffffu, rmax, 1));
            rmax = fmaxf(rmax, __shfl_xor_sync(0xffffffffu, rmax, 2));

            float mold = ms[row];
            float mn = fmaxf(mold, rmax);
            float sum = 0.f;
#pragma unroll
            for (int j = 0; j < 16; ++j) {
                float p = __expf(pr[j] - mn);
                pr[j] = p;
                sum += p;
            }
            sum += __shfl_xor_sync(0xffffffffu, sum, 1);
            sum += __shfl_xor_sync(0xffffffffu, sum, 2);

            if ((tid & 3) == 0) {
                float corr = __expf(mold - mn);
                ls[row] = ls[row] * corr + sum;
                ms[row] = mn;
                osc[row] = corr;
            }
        }
        __syncthreads();

        // --- rescale accumulator, O += P @ V ---
        {
            float c0 = osc[wr * 16 + qr];
            float c1 = osc[wr * 16 + qr + 8];
#pragma unroll
            for (int n = 0; n < 8; ++n) {
                o[n][0] *= c0; o[n][1] *= c0;
                o[n][2] *= c1; o[n][3] *= c1;
            }
        }
        const float* psw = Ps + (wr * 16) * FLP;
#pragma unroll
        for (int kk = 0; kk < 8; ++kk) {
            const float* ap = psw + qr * FLP + kk * 8 + qc;
            uint32_t a0 = f2tf(ap[0]);
            uint32_t a1 = f2tf(ap[8 * FLP]);
            uint32_t a2 = f2tf(ap[4]);
            uint32_t a3 = f2tf(ap[8 * FLP + 4]);
#pragma unroll
            for (int n = 0; n < 8; ++n) {
                const float* bp = Vs + (kk * 8 + qc) * FLV + wc * 64 + n * 8 + qr;
                uint32_t b0 = f2tf(bp[0]);
                uint32_t b1 = f2tf(bp[4 * FLV]);
                mma_tf32(o[n], a0, a1, a2, a3, b0, b1);
            }
        }
    }

    // Final 1/l normalization + store.
    float inv0 = 1.f / ls[wr * 16 + qr];
    float inv1 = 1.f / ls[wr * 16 + qr + 8];
    int srow0 = b * SEQ + qt * FBR + wr * 16 + qr;
#pragma unroll
    for (int n = 0; n < 8; ++n) {
        int col = wc * 64 + n * 8 + qc * 2;
        float* p0 = Og + ((size_t)srow0 * NH + qh) * HD + col;
        float* p1 = Og + ((size_t)(srow0 + 8) * NH + qh) * HD + col;
        *(float2*)p0 = make_float2(o[n][0] * inv0, o[n][1] * inv0);
        *(float2*)p1 = make_float2(o[n][2] * inv1, o[n][3] * inv1);
    }
}

// ---------------------------------------------------------------------------
// Launcher
// ---------------------------------------------------------------------------
extern "C" void kernel_launch(void* const* d_in, const int* in_sizes, int n_in,
                              void* d_out, int out_size)
{
    const float* x  = (const float*)d_in[0];
    const float* wq = (const float*)d_in[1];
    const float* bq = (const float*)d_in[2];
    const float* wk = (const float*)d_in[3];
    const float* bk = (const float*)d_in[4];
    const float* wv = (const float*)d_in[5];
    const float* bv = (const float*)d_in[6];
    const float* wo = (const float*)d_in[7];
    const float* bo = (const float*)d_in[8];
    float* out = (float*)d_out;

    float *q, *k, *v, *attn;
    cudaGetSymbolAddress((void**)&q,    g_q);
    cudaGetSymbolAddress((void**)&k,    g_k);
    cudaGetSymbolAddress((void**)&v,    g_v);
    cudaGetSymbolAddress((void**)&attn, g_attn);

    const int gemm_smem = (2 * 128 * GLA + 2 * 32 * GLB) * sizeof(float);   // 71680
    cudaFuncSetAttribute(tf32_gemm_bias,
                         cudaFuncAttributeMaxDynamicSharedMemorySize, gemm_smem);

    // Projections
    {
        dim3 gq(HIDK / 128, MROWS / 128);
        tf32_gemm_bias<<<gq, 256, gemm_smem>>>(x, wq, bq, q, MROWS, NH * HD, HIDK);
        dim3 gk((NKV * HD) / 128, MROWS / 128);
        tf32_gemm_bias<<<gk, 256, gemm_smem>>>(x, wk, bk, k, MROWS, NKV * HD, HIDK);
        tf32_gemm_bias<<<gk, 256, gemm_smem>>>(x, wv, bv, v, MROWS, NKV * HD, HIDK);
    }

    // Attention
    {
        const int fl_smem = (FBR * FLQ + HD * FLK + FBC * FLV + FBR * FLP + 3 * FBR)
                            * sizeof(float);
        cudaFuncSetAttribute(flash_attn_tf32_kernel,
                             cudaFuncAttributeMaxDynamicSharedMemorySize, fl_smem);
        dim3 ga(SEQ / FBR, NH, BATCH);
        flash_attn_tf32_kernel<<<ga, 256, fl_smem>>>(q, k, v, attn);
    }

    // Output projection
    {
        dim3 go(HIDK / 128, MROWS / 128);
        tf32_gemm_bias<<<go, 256, gemm_smem>>>(attn, wo, bo, out, MROWS, HIDK, HIDK);
    }
}

// round 3
// speedup vs baseline: 3.2728x; 1.3951x over previous
#include <cuda_runtime.h>
#include <math.h>
#include <stdint.h>

// Problem constants
#define HIDK   2048
#define NH     16
#define NKV    4
#define HD     128
#define BATCH  2
#define SEQ    2048
#define MROWS  (BATCH * SEQ)     // 4096

// Scratch (device globals; no allocation allowed)
__device__ float g_q[(size_t)MROWS * NH * HD];
__device__ float g_k[(size_t)MROWS * NKV * HD];
__device__ float g_v[(size_t)MROWS * NKV * HD];
__device__ float g_attn[(size_t)MROWS * NH * HD];

// ---------------------------------------------------------------------------
// Common PTX helpers
// ---------------------------------------------------------------------------
__device__ __forceinline__ uint32_t f2tf(float x) {
    uint32_t r;
    asm("cvt.rna.tf32.f32 %0, %1;" : "=r"(r) : "f"(x));
    return r;
}

__device__ __forceinline__ void mma_tf32(float c[4],
                                         uint32_t a0, uint32_t a1, uint32_t a2, uint32_t a3,
                                         uint32_t b0, uint32_t b1) {
    asm volatile(
        "mma.sync.aligned.m16n8k8.row.col.f32.tf32.tf32.f32 "
        "{%0,%1,%2,%3}, {%4,%5,%6,%7}, {%8,%9}, {%0,%1,%2,%3};"
        : "+f"(c[0]), "+f"(c[1]), "+f"(c[2]), "+f"(c[3])
        : "r"(a0), "r"(a1), "r"(a2), "r"(a3), "r"(b0), "r"(b1));
}

__device__ __forceinline__ uint32_t smaddr(const void* p) {
    return (uint32_t)__cvta_generic_to_shared(p);
}

#define CPA16(dst, src) asm volatile("cp.async.cg.shared.global [%0], [%1], 16;\n" :: "r"(dst), "l"(src))
#define CPCOMMIT()      asm volatile("cp.async.commit_group;\n")
#define CPWAIT1()       asm volatile("cp.async.wait_group 1;\n" ::: "memory")
#define CPWAIT0()       asm volatile("cp.async.wait_group 0;\n" ::: "memory")

// ---------------------------------------------------------------------------
// TF32 tensor-core GEMM: C[M,N] = A[M,K] @ B[K,N] + bias[N]
// (unchanged from round 2)
// ---------------------------------------------------------------------------
#define GLA 36
#define GLB 136

__global__ __launch_bounds__(256)
void tf32_gemm_bias(const float* __restrict__ A,
                    const float* __restrict__ B,
                    const float* __restrict__ bias,
                    float* __restrict__ C,
                    int M, int N, int K)
{
    extern __shared__ float sm[];
    float* As = sm;
    float* Bs = sm + 2 * 128 * GLA;

    const int tid  = threadIdx.x;
    const int lane = tid & 31;
    const int warp = tid >> 5;
    const int wr = warp & 3;
    const int wc = warp >> 2;
    const int qr = lane >> 2;
    const int qc = lane & 3;
    const int rowBase = blockIdx.y * 128;
    const int colBase = blockIdx.x * 128;

    float acc[2][8][4];
#pragma unroll
    for (int m = 0; m < 2; ++m)
#pragma unroll
        for (int n = 0; n < 8; ++n)
#pragma unroll
            for (int i = 0; i < 4; ++i) acc[m][n][i] = 0.f;

    const int steps = K >> 5;

    {
        float* as = As;
        float* bs = Bs;
#pragma unroll
        for (int it = 0; it < 4; ++it) {
            int idx = it * 256 + tid;
            int r = idx >> 3, c = (idx & 7) << 2;
            CPA16(smaddr(as + r * GLA + c), A + (size_t)(rowBase + r) * K + c);
            int rb = idx >> 5, cb = (idx & 31) << 2;
            CPA16(smaddr(bs + rb * GLB + cb), B + (size_t)rb * N + colBase + cb);
        }
        CPCOMMIT();
    }

    for (int s = 0; s < steps; ++s) {
        if (s + 1 < steps) {
            int k0 = (s + 1) << 5;
            float* as = As + ((s + 1) & 1) * 128 * GLA;
            float* bs = Bs + ((s + 1) & 1) * 32 * GLB;
#pragma unroll
            for (int it = 0; it < 4; ++it) {
                int idx = it * 256 + tid;
                int r = idx >> 3, c = (idx & 7) << 2;
                CPA16(smaddr(as + r * GLA + c), A + (size_t)(rowBase + r) * K + k0 + c);
                int rb = idx >> 5, cb = (idx & 31) << 2;
                CPA16(smaddr(bs + rb * GLB + cb), B + (size_t)(k0 + rb) * N + colBase + cb);
            }
            CPCOMMIT();
            CPWAIT1();
        } else {
            CPWAIT0();
        }
        __syncthreads();

        const float* as = As + (s & 1) * 128 * GLA + (wr * 32) * GLA;
        const float* bs = Bs + (s & 1) * 32 * GLB + wc * 64;

#pragma unroll
        for (int kk = 0; kk < 4; ++kk) {
            uint32_t af[2][4];
#pragma unroll
            for (int m = 0; m < 2; ++m) {
                const float* ap = as + (m * 16 + qr) * GLA + kk * 8 + qc;
                af[m][0] = f2tf(ap[0]);
                af[m][1] = f2tf(ap[8 * GLA]);
                af[m][2] = f2tf(ap[4]);
                af[m][3] = f2tf(ap[8 * GLA + 4]);
            }
#pragma unroll
            for (int n = 0; n < 8; ++n) {
                const float* bp = bs + (kk * 8 + qc) * GLB + n * 8 + qr;
                uint32_t b0 = f2tf(bp[0]);
                uint32_t b1 = f2tf(bp[4 * GLB]);
                mma_tf32(acc[0][n], af[0][0], af[0][1], af[0][2], af[0][3], b0, b1);
                mma_tf32(acc[1][n], af[1][0], af[1][1], af[1][2], af[1][3], b0, b1);
            }
        }
        __syncthreads();
    }

#pragma unroll
    for (int m = 0; m < 2; ++m) {
        int row = rowBase + wr * 32 + m * 16 + qr;
#pragma unroll
        for (int n = 0; n < 8; ++n) {
            int col = colBase + wc * 64 + n * 8 + qc * 2;
            float bx = bias[col], by = bias[col + 1];
            float2 v0 = make_float2(acc[m][n][0] + bx, acc[m][n][1] + by);
            float2 v1 = make_float2(acc[m][n][2] + bx, acc[m][n][3] + by);
            *(float2*)(C + (size_t)row * N + col)       = v0;
            *(float2*)(C + (size_t)(row + 8) * N + col) = v1;
        }
    }
}

// ---------------------------------------------------------------------------
// Flash attention v3: Q frags in registers, K pair-packed (float2 B frags),
// P pair-permuted (float2 A frags + float4 softmax), V natural (conflict-free).
// ---------------------------------------------------------------------------
#define FBR 64
#define FBC 64
#define QPITCH 132   // Q staging pitch  (%32==4)
#define KPITCH 132   // Kp pitch, token-major pair-packed (%32==4)
#define VPITCH 136   // Vs pitch, natural [token][d] (%32==8)
#define PPITCH 68    // Ps pitch (%32==4)

__global__ __launch_bounds__(256)
void flash_attn_tf32_kernel(const float* __restrict__ Q,
                            const float* __restrict__ Kg,
                            const float* __restrict__ Vg,
                            float* __restrict__ Og)
{
    extern __shared__ float sm[];
    float* Qs  = sm;                        // [64][QPITCH] (staging only)
    float* Kp  = Qs + FBR * QPITCH;         // [64 tokens][KPITCH] pair-packed d
    float* Vs  = Kp + FBC * KPITCH;         // [64 tokens][VPITCH] natural
    float* Ps  = Vs + FBC * VPITCH;         // [64][PPITCH] pair-permuted cols
    float* ms  = Ps + FBR * PPITCH;
    float* ls  = ms + FBR;
    float* osc = ls + FBR;

    const int tid  = threadIdx.x;
    const int lane = tid & 31;
    const int warp = tid >> 5;
    const int wr = warp & 3;                // 4 warp rows x 16
    const int wc = warp >> 2;               // 2 warp cols
    const int qr = lane >> 2;
    const int qc = lane & 3;

    const int qt  = blockIdx.x;
    const int qh  = blockIdx.y;
    const int b   = blockIdx.z;
    const int kvh = qh >> 2;

    const float scale = 0.08838834764831845f; // 1/sqrt(128)

    // Stage Q tile (64 x 128), pre-scaled, row-major.
    const float* Qbase = Q + ((size_t)(b * SEQ + qt * FBR) * NH + qh) * HD;
#pragma unroll
    for (int it = 0; it < 8; ++it) {
        int idx = it * 256 + tid;
        int r = idx >> 5;
        int c = (idx & 31) << 2;
        float4 v = *(const float4*)(Qbase + (size_t)r * NH * HD + c);
        v.x *= scale; v.y *= scale; v.z *= scale; v.w *= scale;
        *(float4*)(Qs + r * QPITCH + c) = v;
    }
    if (tid < FBR) { ms[tid] = -1e30f; ls[tid] = 0.f; }
    __syncthreads();

    // Convert Q fragments to registers once (reused every kt iteration).
    uint32_t qa[16][4];
    {
        const float* qsw = Qs + (wr * 16 + qr) * QPITCH;
#pragma unroll
        for (int kk = 0; kk < 16; ++kk) {
            const float* ap = qsw + kk * 8 + qc;
            qa[kk][0] = f2tf(ap[0]);
            qa[kk][1] = f2tf(ap[8 * QPITCH]);
            qa[kk][2] = f2tf(ap[4]);
            qa[kk][3] = f2tf(ap[8 * QPITCH + 4]);
        }
    }

    float o[8][4];
#pragma unroll
    for (int n = 0; n < 8; ++n)
#pragma unroll
        for (int i = 0; i < 4; ++i) o[n][i] = 0.f;

    for (int kt = 0; kt <= qt; ++kt) {
        __syncthreads();   // prior-iter reads of Kp/Vs/Ps complete

        const float* Kbase = Kg + ((size_t)(b * SEQ + kt * FBC) * NKV + kvh) * HD;
        const float* Vbase = Vg + ((size_t)(b * SEQ + kt * FBC) * NKV + kvh) * HD;

        // Fill Kp: token-major, d pair-packed: pairs (d, d+4) adjacent.
#pragma unroll
        for (int it = 0; it < 4; ++it) {
            int idx = it * 256 + tid;      // 0..1023
            int r = idx >> 4;              // token 0..63
            int c = (idx & 15) << 3;       // d group of 8
            const float* src = Kbase + (size_t)r * NKV * HD + c;
            float4 x0 = *(const float4*)(src);
            float4 x1 = *(const float4*)(src + 4);
            float* dst = Kp + r * KPITCH + c;
            *(float2*)(dst + 0) = make_float2(x0.x, x1.x);
            *(float2*)(dst + 2) = make_float2(x0.y, x1.y);
            *(float2*)(dst + 4) = make_float2(x0.z, x1.z);
            *(float2*)(dst + 6) = make_float2(x0.w, x1.w);
        }
        // Fill Vs: natural [token][d], float4 conflict-free.
#pragma unroll
        for (int it = 0; it < 8; ++it) {
            int idx = it * 256 + tid;
            int r = idx >> 5;
            int c = (idx & 31) << 2;
            *(float4*)(Vs + r * VPITCH + c) =
                *(const float4*)(Vbase + (size_t)r * NKV * HD + c);
        }
        __syncthreads();

        // --- S = Q @ K^T (warp: 16 rows x 32 cols); B frags = float2 from Kp ---
        float sacc[4][4];
#pragma unroll
        for (int n = 0; n < 4; ++n)
#pragma unroll
            for (int i = 0; i < 4; ++i) sacc[n][i] = 0.f;

#pragma unroll
        for (int kk = 0; kk < 16; ++kk) {
#pragma unroll
            for (int n = 0; n < 4; ++n) {
                const float* bp = Kp + (wc * 32 + n * 8 + qr) * KPITCH + kk * 8 + qc * 2;
                float2 bv = *(const float2*)bp;
                mma_tf32(sacc[n], qa[kk][0], qa[kk][1], qa[kk][2], qa[kk][3],
                         f2tf(bv.x), f2tf(bv.y));
            }
        }

        // Causal mask (original column indices) + store P pair-permuted.
        int row0 = wr * 16 + qr;
        if (kt == qt) {
#pragma unroll
            for (int n = 0; n < 4; ++n) {
                int col = wc * 32 + n * 8 + qc * 2;
                if (col > row0)         sacc[n][0] = -1e30f;
                if (col + 1 > row0)     sacc[n][1] = -1e30f;
                if (col > row0 + 8)     sacc[n][2] = -1e30f;
                if (col + 1 > row0 + 8) sacc[n][3] = -1e30f;
            }
        }
        {
            int pc = (qc & 1) * 4 + (qc >> 1);   // permuted pos of col j=2*qc
#pragma unroll
            for (int n = 0; n < 4; ++n) {
                int pos = (wc * 4 + n) * 8 + pc;
                Ps[row0 * PPITCH + pos]           = sacc[n][0];
                Ps[row0 * PPITCH + pos + 2]       = sacc[n][1];
                Ps[(row0 + 8) * PPITCH + pos]     = sacc[n][2];
                Ps[(row0 + 8) * PPITCH + pos + 2] = sacc[n][3];
            }
        }
        __syncthreads();

        // --- online softmax: 4 threads per row, float4 vectorized ---
        {
            int row = tid >> 2;
            float* pr = Ps + row * PPITCH + (tid & 3) * 16;
            float4 p0 = *(float4*)(pr);
            float4 p1 = *(float4*)(pr + 4);
            float4 p2 = *(float4*)(pr + 8);
            float4 p3 = *(float4*)(pr + 12);
            float rmax = fmaxf(fmaxf(fmaxf(p0.x, p0.y), fmaxf(p0.z, p0.w)),
                               fmaxf(fmaxf(p1.x, p1.y), fmaxf(p1.z, p1.w)));
            rmax = fmaxf(rmax, fmaxf(fmaxf(fmaxf(p2.x, p2.y), fmaxf(p2.z, p2.w)),
                                     fmaxf(fmaxf(p3.x, p3.y), fmaxf(p3.z, p3.w))));
            rmax = fmaxf(rmax, __shfl_xor_sync(0xffffffffu, rmax, 1));
            rmax = fmaxf(rmax, __shfl_xor_sync(0xffffffffu, rmax, 2));

            float mold = ms[row];
            float mn = fmaxf(mold, rmax);
            p0.x = __expf(p0.x - mn); p0.y = __expf(p0.y - mn);
            p0.z = __expf(p0.z - mn); p0.w = __expf(p0.w - mn);
            p1.x = __expf(p1.x - mn); p1.y = __expf(p1.y - mn);
            p1.z = __expf(p1.z - mn); p1.w = __expf(p1.w - mn);
            p2.x = __expf(p2.x - mn); p2.y = __expf(p2.y - mn);
            p2.z = __expf(p2.z - mn); p2.w = __expf(p2.w - mn);
            p3.x = __expf(p3.x - mn); p3.y = __expf(p3.y - mn);
            p3.z = __expf(p3.z - mn); p3.w = __expf(p3.w - mn);
            *(float4*)(pr)      = p0;
            *(float4*)(pr + 4)  = p1;
            *(float4*)(pr + 8)  = p2;
            *(float4*)(pr + 12) = p3;
            float sum = (p0.x + p0.y + p0.z + p0.w) + (p1.x + p1.y + p1.z + p1.w)
                      + (p2.x + p2.y + p2.z + p2.w) + (p3.x + p3.y + p3.z + p3.w);
            sum += __shfl_xor_sync(0xffffffffu, sum, 1);
            sum += __shfl_xor_sync(0xffffffffu, sum, 2);

            if ((tid & 3) == 0) {
                float corr = __expf(mold - mn);
                ls[row] = ls[row] * corr + sum;
                ms[row] = mn;
                osc[row] = corr;
            }
        }
        __syncthreads();

        // --- rescale accumulator, O += P @ V ---
        {
            float c0 = osc[wr * 16 + qr];
            float c1 = osc[wr * 16 + qr + 8];
#pragma unroll
            for (int n = 0; n < 8; ++n) {
                o[n][0] *= c0; o[n][1] *= c0;
                o[n][2] *= c1; o[n][3] *= c1;
            }
        }
#pragma unroll
        for (int kk = 0; kk < 8; ++kk) {
            const float* ap = Ps + (wr * 16 + qr) * PPITCH + kk * 8 + qc * 2;
            float2 av0 = *(const float2*)ap;
            float2 av1 = *(const float2*)(ap + 8 * PPITCH);
            uint32_t a0 = f2tf(av0.x);   // (row qr,   k)
            uint32_t a1 = f2tf(av1.x);   // (row qr+8, k)
            uint32_t a2 = f2tf(av0.y);   // (row qr,   k+4)
            uint32_t a3 = f2tf(av1.y);   // (row qr+8, k+4)
#pragma unroll
            for (int n = 0; n < 8; ++n) {
                const float* bp = Vs + (kk * 8 + qc) * VPITCH + wc * 64 + n * 8 + qr;
                uint32_t b0 = f2tf(bp[0]);
                uint32_t b1 = f2tf(bp[4 * VPITCH]);
                mma_tf32(o[n], a0, a1, a2, a3, b0, b1);
            }
        }
    }

    // Final 1/l normalization + store.
    float inv0 = 1.f / ls[wr * 16 + qr];
    float inv1 = 1.f / ls[wr * 16 + qr + 8];
    int srow0 = b * SEQ + qt * FBR + wr * 16 + qr;
#pragma unroll
    for (int n = 0; n < 8; ++n) {
        int col = wc * 64 + n * 8 + qc * 2;
        float* p0 = Og + ((size_t)srow0 * NH + qh) * HD + col;
        float* p1 = Og + ((size_t)(srow0 + 8) * NH + qh) * HD + col;
        *(float2*)p0 = make_float2(o[n][0] * inv0, o[n][1] * inv0);
        *(float2*)p1 = make_float2(o[n][2] * inv1, o[n][3] * inv1);
    }
}

// ---------------------------------------------------------------------------
// Launcher
// ---------------------------------------------------------------------------
extern "C" void kernel_launch(void* const* d_in, const int* in_sizes, int n_in,
                              void* d_out, int out_size)
{
    const float* x  = (const float*)d_in[0];
    const float* wq = (const float*)d_in[1];
    const float* bq = (const float*)d_in[2];
    const float* wk = (const float*)d_in[3];
    const float* bk = (const float*)d_in[4];
    const float* wv = (const float*)d_in[5];
    const float* bv = (const float*)d_in[6];
    const float* wo = (const float*)d_in[7];
    const float* bo = (const float*)d_in[8];
    float* out = (float*)d_out;

    float *q, *k, *v, *attn;
    cudaGetSymbolAddress((void**)&q,    g_q);
    cudaGetSymbolAddress((void**)&k,    g_k);
    cudaGetSymbolAddress((void**)&v,    g_v);
    cudaGetSymbolAddress((void**)&attn, g_attn);

    const int gemm_smem = (2 * 128 * GLA + 2 * 32 * GLB) * sizeof(float);
    cudaFuncSetAttribute(tf32_gemm_bias,
                         cudaFuncAttributeMaxDynamicSharedMemorySize, gemm_smem);

    // Projections
    {
        dim3 gq(HIDK / 128, MROWS / 128);
        tf32_gemm_bias<<<gq, 256, gemm_smem>>>(x, wq, bq, q, MROWS, NH * HD, HIDK);
        dim3 gk((NKV * HD) / 128, MROWS / 128);
        tf32_gemm_bias<<<gk, 256, gemm_smem>>>(x, wk, bk, k, MROWS, NKV * HD, HIDK);
        tf32_gemm_bias<<<gk, 256, gemm_smem>>>(x, wv, bv, v, MROWS, NKV * HD, HIDK);
    }

    // Attention
    {
        const int fl_smem = (FBR * QPITCH + FBC * KPITCH + FBC * VPITCH
                             + FBR * PPITCH + 3 * FBR) * sizeof(float);
        cudaFuncSetAttribute(flash_attn_tf32_kernel,
                             cudaFuncAttributeMaxDynamicSharedMemorySize, fl_smem);
        dim3 ga(SEQ / FBR, NH, BATCH);
        flash_attn_tf32_kernel<<<ga, 256, fl_smem>>>(q, k, v, attn);
    }

    // Output projection
    {
        dim3 go(HIDK / 128, MROWS / 128);
        tf32_gemm_bias<<<go, 256, gemm_smem>>>(attn, wo, bo, out, MROWS, HIDK, HIDK);
    }
}